// round 13
// baseline (speedup 1.0000x reference)
#include <cuda_runtime.h>
#include <cuda_bf16.h>

// NeuSSampler inverse-CDF importance sampling — v13: v12 pipeline x 2 rays
// per warp (ILP=2). weights [R,128,1] f32, existing_bins [R,129] f32,
// nears [R,1], fars [R,1] -> out [R,65] f32.
//
// Each warp processes rays {g, g + R/2} as two fully independent streams;
// ptxas interleaves them to absorb the shfl/LDS/LDG latency that capped
// the single-stream version at ~71% issue.
//
// Per-ray pipeline (all pieces bench-validated in earlier rounds):
//   scan: float4 weights + 5-step shfl scan, histogram padding folded.
//   owner chunk p: 5-probe shfl ladder over sorted chunk tops.
//   sub-segment r: SWAR byte-compare on packed boundaries m1..m3.
//   cdf endpoints: scalar LDS from per-warp cdf table.
//   bin endpoints: LDG from prefetched (L1-resident) ebins row.

#define S_SAMP 128
#define NB 65
#define HIST_PAD 1e-5f
#define EPS_V 1e-5f
#define WPB 8
#define NTHREADS (WPB * 32)
#define INV_NB (1.0f / 65.0f)
#define FULL 0xffffffffu

struct RayState {
    float c0, c1, c2, c3, c4;
    unsigned M;
    const float* ebrow;
    float nearv, dfn;
    float* orow;
    bool act;
};

__global__ __launch_bounds__(NTHREADS)
void neus_sampler_kernel(const float* __restrict__ weights,
                         const float* __restrict__ ebins,
                         const float* __restrict__ nears,
                         const float* __restrict__ fars,
                         float* __restrict__ out,
                         int R)
{
    __shared__ __align__(16) float cdf_sm[WPB][2][132];

    const int warp = threadIdx.x >> 5;
    const int lane = threadIdx.x & 31;
    const unsigned half = ((unsigned)R + 1u) >> 1;
    const unsigned g = blockIdx.x * WPB + warp;
    if (g >= half) return;

    const int k = lane * 4;
    RayState rs[2];
    rs[0].act = true;
    rs[1].act = (g + half) < (unsigned)R;

    // ================= phase A: build cdf tables (both rays) ==============
    #pragma unroll
    for (int t = 0; t < 2; t++) {
        if (!rs[t].act) continue;
        const unsigned ray = g + t * half;

        const float* ebrow = ebins + ray * 129u;
        rs[t].ebrow = ebrow;
        if (lane < 5) {  // warm whole 516B row into L1
            asm volatile("prefetch.global.L1 [%0];" :: "l"(ebrow + lane * 32));
        }
        const float4 wv =
            *reinterpret_cast<const float4*>(weights + ray * 128u + k);
        const float nearv = nears[ray];
        const float farv  = fars[ray];

        const float l0 = wv.x;
        const float l1 = l0 + wv.y;
        const float l2 = l1 + wv.z;
        const float l3 = l2 + wv.w;

        float pre = l3;
        #pragma unroll
        for (int off = 1; off < 32; off <<= 1) {
            float v = __shfl_up_sync(FULL, pre, off);
            if (lane >= off) pre += v;
        }
        const float total_raw = __shfl_sync(FULL, pre, 31);
        const float excl      = pre - l3;

        const float total_wp = total_raw + (float)S_SAMP * HIST_PAD;
        const float padding  = fmaxf(0.0f, EPS_V - total_wp);
        const float inv_wsum = __fdividef(1.0f, total_wp + padding);
        const float step     = HIST_PAD + padding * (1.0f / (float)S_SAMP);

        const float kf = (float)k;
        const float c0 = fmaf(kf,        step, excl     ) * inv_wsum;
        const float c1 = fmaf(kf + 1.0f, step, excl + l0) * inv_wsum;
        const float c2 = fmaf(kf + 2.0f, step, excl + l1) * inv_wsum;
        const float c3 = fmaf(kf + 3.0f, step, excl + l2) * inv_wsum;
        const float c4 = fmaf(kf + 4.0f, step, excl + l3) * inv_wsum;
        rs[t].c0 = c0; rs[t].c1 = c1; rs[t].c2 = c2;
        rs[t].c3 = c3; rs[t].c4 = c4;

        const int m1 = __float2int_rd(fmaf(65.0f, c1, 0.5f));
        const int m2 = __float2int_rd(fmaf(65.0f, c2, 0.5f));
        const int m3 = __float2int_rd(fmaf(65.0f, c3, 0.5f));
        rs[t].M = (unsigned)m1 | ((unsigned)m2 << 8) | ((unsigned)m3 << 16);

        float* cw = cdf_sm[warp][t];
        float4 cv4; cv4.x = c0; cv4.y = c1; cv4.z = c2; cv4.w = c3;
        *reinterpret_cast<float4*>(cw + k) = cv4;
        if (lane == 31) cw[128] = c4;

        rs[t].nearv = nearv;
        rs[t].dfn   = farv - nearv;
        rs[t].orow  = out + ray * 65u;
    }

    __syncwarp(FULL);   // single barrier covers both rays' STS

    // ================= phase B: queries (both rays, interleaved) ===========
    const float u0 = ((float)lane + 0.5f)  * INV_NB;
    const float u1 = ((float)lane + 32.5f) * INV_NB;
    const unsigned J0 = (unsigned)lane        * 0x01010101u;
    const unsigned J1 = (unsigned)(lane + 32) * 0x01010101u;

    #pragma unroll
    for (int t = 0; t < 2; t++) {
        if (!rs[t].act) continue;
        const float c0 = rs[t].c0;
        const float* cw = cdf_sm[warp][t];

        int p0 = 0, p1 = 0;
        {
            const float cs = __shfl_sync(FULL, c0, 16);
            if (cs <= u0) p0 = 16;
            if (cs <= u1) p1 = 16;
        }
        #pragma unroll
        for (int st = 8; st >= 1; st >>= 1) {
            const float a0 = __shfl_sync(FULL, c0, p0 + st);
            const float a1 = __shfl_sync(FULL, c0, p1 + st);
            if (a0 <= u0) p0 += st;
            if (a1 <= u1) p1 += st;
        }

        const unsigned M0 = __shfl_sync(FULL, rs[t].M, p0);
        const unsigned M1 = __shfl_sync(FULL, rs[t].M, p1);
        const int r0 = __popc(((J0 | 0x80808080u) - M0) & 0x00808080u);
        const int r1 = __popc(((J1 | 0x80808080u) - M1) & 0x00808080u);

        const int i0 = p0 * 4 + r0;
        const int i1 = p1 * 4 + r1;

        const float clo0 = cw[i0], chi0 = cw[i0 + 1];
        const float clo1 = cw[i1], chi1 = cw[i1 + 1];
        const float blo0 = __ldg(rs[t].ebrow + i0);
        const float bhi0 = __ldg(rs[t].ebrow + i0 + 1);
        const float blo1 = __ldg(rs[t].ebrow + i1);
        const float bhi1 = __ldg(rs[t].ebrow + i1 + 1);

        const float t0  = (u0 - clo0) * __fdividef(1.0f, chi0 - clo0);
        const float t1  = (u1 - clo1) * __fdividef(1.0f, chi1 - clo1);
        const float bb0 = fmaf(t0, bhi0 - blo0, blo0);
        const float bb1 = fmaf(t1, bhi1 - blo1, blo1);
        rs[t].orow[lane]      = fmaf(bb0, rs[t].dfn, rs[t].nearv);
        rs[t].orow[lane + 32] = fmaf(bb1, rs[t].dfn, rs[t].nearv);

        // j = 64
        {
            const float u = 64.5f * INV_NB;
            const unsigned msk = __ballot_sync(FULL, c0 <= u);
            const int pt = 31 - __clz(msk);
            const unsigned Mt = __shfl_sync(FULL, rs[t].M, pt);
            if (lane == 0) {
                const unsigned Jt = 64u * 0x01010101u;
                const int rt = __popc(((Jt | 0x80808080u) - Mt) & 0x00808080u);
                const int it = pt * 4 + rt;
                const float clo = cw[it], chi = cw[it + 1];
                const float blo = __ldg(rs[t].ebrow + it);
                const float bhi = __ldg(rs[t].ebrow + it + 1);
                const float tv = (u - clo) * __fdividef(1.0f, chi - clo);
                const float bb = fmaf(tv, bhi - blo, blo);
                rs[t].orow[64] = fmaf(bb, rs[t].dfn, rs[t].nearv);
            }
        }
    }
}

extern "C" void kernel_launch(void* const* d_in, const int* in_sizes, int n_in,
                              void* d_out, int out_size) {
    const float* weights = (const float*)d_in[0];
    const float* ebins   = (const float*)d_in[1];
    const float* nears   = (const float*)d_in[2];
    const float* fars    = (const float*)d_in[3];
    float* out = (float*)d_out;

    const int R = in_sizes[2];  // nears has R elements
    const unsigned half = ((unsigned)R + 1u) >> 1;
    const int grid = (int)((half + WPB - 1) / WPB);
    neus_sampler_kernel<<<grid, NTHREADS>>>(weights, ebins, nears, fars, out, R);
}